// round 10
// baseline (speedup 1.0000x reference)
#include <cuda_runtime.h>
#include <cuda_bf16.h>
#include <stdint.h>
#include <math.h>

// Problem constants
constexpr int B  = 2;
constexpr int S  = 2048;
constexpr int D  = 1024;
constexpr int H  = 16;
constexpr int HD = 64;
constexpr int M  = B * S;          // 4096 rows
static_assert(H * HD == D, "");

typedef __nv_bfloat16 bf16;

// ---------------------------------------------------------------------------
// Persistent split-bf16 planes (static device globals — allocation-free)
// ---------------------------------------------------------------------------
__device__ bf16 g_xh[(size_t)M * D], g_xl[(size_t)M * D];
__device__ bf16 g_Qh[(size_t)M * D], g_Ql[(size_t)M * D];
__device__ bf16 g_Kh[(size_t)M * D], g_Kl[(size_t)M * D];
__device__ bf16 g_Vh[(size_t)M * D], g_Vl[(size_t)M * D];
__device__ bf16 g_Oh[(size_t)M * D], g_Ol[(size_t)M * D];
__device__ bf16 g_WTh[4][(size_t)D * D], g_WTl[4][(size_t)D * D];  // [n][k]

// ---------------------------------------------------------------------------
// Helpers
// ---------------------------------------------------------------------------
__device__ __forceinline__ void split_bf16(float x, bf16& h, bf16& l) {
    h = __float2bfloat16(x);
    l = __float2bfloat16(x - __bfloat162float(h));
}
__device__ __forceinline__ unsigned pack2(bf16 a, bf16 b) {
    __nv_bfloat162 p; p.x = a; p.y = b;
    return *(unsigned*)&p;
}
__device__ __forceinline__ uint32_t smem_u32(const void* p) {
    return (uint32_t)__cvta_generic_to_shared(p);
}
__device__ __forceinline__ void cpasync16(uint32_t dst, const void* src) {
    asm volatile("cp.async.cg.shared.global [%0], [%1], 16;\n" :: "r"(dst), "l"(src));
}
__device__ __forceinline__ void cpcommit() {
    asm volatile("cp.async.commit_group;\n");
}
template <int N>
__device__ __forceinline__ void cpwait() {
    asm volatile("cp.async.wait_group %0;\n" :: "n"(N));
}

// D += A(16x16) * B(16x8), bf16 in, fp32 acc.
__device__ __forceinline__ void mma16816(float* c, const unsigned* a, const unsigned* b) {
    asm volatile(
        "mma.sync.aligned.m16n8k16.row.col.f32.bf16.bf16.f32 "
        "{%0,%1,%2,%3},{%4,%5,%6,%7},{%8,%9},{%0,%1,%2,%3};\n"
        : "+f"(c[0]), "+f"(c[1]), "+f"(c[2]), "+f"(c[3])
        : "r"(a[0]), "r"(a[1]), "r"(a[2]), "r"(a[3]), "r"(b[0]), "r"(b[1]));
}
__device__ __forceinline__ void ldmx4(unsigned* r, uint32_t addr) {
    asm volatile("ldmatrix.sync.aligned.m8n8.x4.shared.b16 {%0,%1,%2,%3}, [%4];\n"
                 : "=r"(r[0]), "=r"(r[1]), "=r"(r[2]), "=r"(r[3]) : "r"(addr));
}
__device__ __forceinline__ void ldmx4t(unsigned* r, uint32_t addr) {
    asm volatile("ldmatrix.sync.aligned.m8n8.x4.trans.shared.b16 {%0,%1,%2,%3}, [%4];\n"
                 : "=r"(r[0]), "=r"(r[1]), "=r"(r[2]), "=r"(r[3]) : "r"(addr));
}
template <int SK>
__device__ __forceinline__ uint32_t addrA(const bf16* base, int row0, int k0, int lane) {
    int g = lane >> 3, lr = lane & 7;
    return smem_u32(base + (row0 + (g & 1) * 8 + lr) * SK + k0 + (g >> 1) * 8);
}
template <int SK>
__device__ __forceinline__ uint32_t addrB(const bf16* base, int n0, int k0, int lane) {
    int g = lane >> 3, lr = lane & 7;
    return smem_u32(base + (n0 + (g >> 1) * 8 + lr) * SK + k0 + (g & 1) * 8);
}
template <int SK>
__device__ __forceinline__ uint32_t addrBT(const bf16* base, int kk0, int d0, int lane) {
    int g = lane >> 3, lr = lane & 7;
    return smem_u32(base + (kk0 + (g & 1) * 8 + lr) * SK + d0 + (g >> 1) * 8);
}

// ---------------------------------------------------------------------------
// Prep 1: split x into hi/lo bf16 planes.
// ---------------------------------------------------------------------------
__global__ __launch_bounds__(256) void xprep_kernel(const float* __restrict__ x,
                                                    bf16* __restrict__ xh,
                                                    bf16* __restrict__ xl) {
    size_t i4 = (size_t)blockIdx.x * 256 + threadIdx.x;
    float4 v = *(const float4*)(x + i4 * 4);
    bf16 h0, l0, h1, l1, h2, l2, h3, l3;
    split_bf16(v.x, h0, l0); split_bf16(v.y, h1, l1);
    split_bf16(v.z, h2, l2); split_bf16(v.w, h3, l3);
    *(uint2*)(xh + i4 * 4) = make_uint2(pack2(h0, h1), pack2(h2, h3));
    *(uint2*)(xl + i4 * 4) = make_uint2(pack2(l0, l1), pack2(l2, l3));
}

// ---------------------------------------------------------------------------
// Prep 2 (fused over 4 weights): transpose-split W [K][N] -> Th/Tl [N][K].
// ---------------------------------------------------------------------------
struct WPrepPtrs {
    const float* W[4];
    bf16* Th[4];
    bf16* Tl[4];
};

__global__ __launch_bounds__(256) void wprep_kernel(WPrepPtrs pp) {
    __shared__ float tile[32][33];
    const int z  = blockIdx.z;
    const float* W = pp.W[z];
    bf16* Th = pp.Th[z];
    bf16* Tl = pp.Tl[z];
    int n0 = blockIdx.x * 32, k0 = blockIdx.y * 32;
    int tx = threadIdx.x, ty = threadIdx.y;   // 32 x 8
    #pragma unroll
    for (int j = 0; j < 4; j++)
        tile[ty + j * 8][tx] = W[(size_t)(k0 + ty + j * 8) * D + n0 + tx];
    __syncthreads();
    #pragma unroll
    for (int j = 0; j < 4; j++) {
        int nn = ty + j * 8;
        float v = tile[tx][nn];
        bf16 h, l;
        split_bf16(v, h, l);
        Th[(size_t)(n0 + nn) * D + k0 + tx] = h;
        Tl[(size_t)(n0 + nn) * D + k0 + tx] = l;
    }
}

// ---------------------------------------------------------------------------
// Split-bf16 tensor-core GEMM core (shared by fused-QKV and O-projection).
// C[M,N] = A[M,K] @ B^T[N,K] + bias.  128x128 tile, BK=32, 8 warps (4x2),
// cp.async double-buffered.
// ---------------------------------------------------------------------------
constexpr int GSK   = 40;                       // smem k-stride (32 + 8 pad)
constexpr int GPL   = 128 * GSK;                // plane elems
constexpr int GSTG  = 4 * GPL;                  // stage elems (Ah Al Bh Bl)
constexpr int GEMM_SMEM_BYTES = 2 * GSTG * 2;   // 2 stages * bf16

__device__ __forceinline__ void gemm_core(
    const bf16* __restrict__ Ah_g, const bf16* __restrict__ Al_g,
    const bf16* __restrict__ Bh_g, const bf16* __restrict__ Bl_g,
    const float* __restrict__ bias,
    float* __restrict__ Cf, bf16* __restrict__ Ch, bf16* __restrict__ Cl,
    char* smraw, int m0, int n0)
{
    bf16* sm = (bf16*)smraw;

    const int t    = threadIdx.x;
    const int lane = t & 31;
    const int wid  = t >> 5;
    const int wm   = wid >> 1;       // 0..3
    const int wn   = wid & 1;        // 0..1
    constexpr int NIT = D / 32;      // 32

    float acc[2][8][4];
    #pragma unroll
    for (int i = 0; i < 2; i++)
        #pragma unroll
        for (int j = 0; j < 8; j++)
            #pragma unroll
            for (int c = 0; c < 4; c++) acc[i][j][c] = 0.f;

    auto load_stage = [&](int st, int k0) {
        bf16* sAh = sm + st * GSTG;
        bf16* sAl = sAh + GPL;
        bf16* sBh = sAl + GPL;
        bf16* sBl = sBh + GPL;
        #pragma unroll
        for (int i = 0; i < 2; i++) {
            int f   = t + i * 256;         // 0..511
            int row = f >> 2;              // 0..127
            int ce  = (f & 3) * 8;         // k elem offset (16B chunks)
            size_t ga = (size_t)(m0 + row) * D + k0 + ce;
            size_t gb = (size_t)(n0 + row) * D + k0 + ce;
            cpasync16(smem_u32(sAh + row * GSK + ce), Ah_g + ga);
            cpasync16(smem_u32(sAl + row * GSK + ce), Al_g + ga);
            cpasync16(smem_u32(sBh + row * GSK + ce), Bh_g + gb);
            cpasync16(smem_u32(sBl + row * GSK + ce), Bl_g + gb);
        }
        cpcommit();
    };

    load_stage(0, 0);
    int st = 0;
    for (int it = 0; it < NIT; it++) {
        if (it + 1 < NIT) { load_stage(st ^ 1, (it + 1) * 32); cpwait<1>(); }
        else             { cpwait<0>(); }
        __syncthreads();

        bf16* sAh = sm + st * GSTG;
        bf16* sAl = sAh + GPL;
        bf16* sBh = sAl + GPL;
        bf16* sBl = sBh + GPL;

        #pragma unroll
        for (int ks = 0; ks < 32; ks += 16) {
            unsigned bh[8][2], bl[8][2];
            #pragma unroll
            for (int nt = 0; nt < 4; nt++) {
                ldmx4(&bh[nt * 2][0], addrB<GSK>(sBh, wn * 64 + nt * 16, ks, lane));
                ldmx4(&bl[nt * 2][0], addrB<GSK>(sBl, wn * 64 + nt * 16, ks, lane));
            }
            #pragma unroll
            for (int ms = 0; ms < 2; ms++) {
                unsigned ah[4], al[4];
                ldmx4(ah, addrA<GSK>(sAh, wm * 32 + ms * 16, ks, lane));
                ldmx4(al, addrA<GSK>(sAl, wm * 32 + ms * 16, ks, lane));
                #pragma unroll
                for (int ns = 0; ns < 8; ns++) {
                    mma16816(acc[ms][ns], ah, bh[ns]);
                    mma16816(acc[ms][ns], ah, bl[ns]);
                    mma16816(acc[ms][ns], al, bh[ns]);
                }
            }
        }
        __syncthreads();
        st ^= 1;
    }

    // Epilogue
    #pragma unroll
    for (int ms = 0; ms < 2; ms++) {
        int row = m0 + wm * 32 + ms * 16 + (lane >> 2);
        #pragma unroll
        for (int ns = 0; ns < 8; ns++) {
            int col = n0 + wn * 64 + ns * 8 + (lane & 3) * 2;
            float b0 = bias[col], b1 = bias[col + 1];
            float v00 = acc[ms][ns][0] + b0, v01 = acc[ms][ns][1] + b1;
            float v10 = acc[ms][ns][2] + b0, v11 = acc[ms][ns][3] + b1;
            if (Cf) {
                *(float2*)(Cf + (size_t)row * D + col)       = make_float2(v00, v01);
                *(float2*)(Cf + (size_t)(row + 8) * D + col) = make_float2(v10, v11);
            } else {
                bf16 h0, l0, h1, l1;
                split_bf16(v00, h0, l0); split_bf16(v01, h1, l1);
                *(unsigned*)(Ch + (size_t)row * D + col) = pack2(h0, h1);
                *(unsigned*)(Cl + (size_t)row * D + col) = pack2(l0, l1);
                split_bf16(v10, h0, l0); split_bf16(v11, h1, l1);
                *(unsigned*)(Ch + (size_t)(row + 8) * D + col) = pack2(h0, h1);
                *(unsigned*)(Cl + (size_t)(row + 8) * D + col) = pack2(l0, l1);
            }
        }
    }
}

// Fused Q/K/V projection: grid.z selects weight/bias/output.
struct QKVParams {
    const bf16* Wh[3];
    const bf16* Wl[3];
    const float* bias[3];
    bf16* Ch[3];
    bf16* Cl[3];
};

__global__ __launch_bounds__(256) void qkv_gemm_kernel(
    const bf16* __restrict__ xh, const bf16* __restrict__ xl, QKVParams pp)
{
    extern __shared__ __align__(16) char smraw[];
    const int z = blockIdx.z;
    gemm_core(xh, xl, pp.Wh[z], pp.Wl[z], pp.bias[z],
              nullptr, pp.Ch[z], pp.Cl[z],
              smraw, blockIdx.y * 128, blockIdx.x * 128);
}

// O projection (fp32 output).
__global__ __launch_bounds__(256) void oproj_gemm_kernel(
    const bf16* __restrict__ Ah, const bf16* __restrict__ Al,
    const bf16* __restrict__ Bh, const bf16* __restrict__ Bl,
    const float* __restrict__ bias, float* __restrict__ Cf)
{
    extern __shared__ __align__(16) char smraw[];
    gemm_core(Ah, Al, Bh, Bl, bias, Cf, nullptr, nullptr,
              smraw, blockIdx.y * 128, blockIdx.x * 128);
}

// ---------------------------------------------------------------------------
// Split-bf16 HMMA flash attention with DOUBLE-BUFFERED K/V stages.
// CTA = 64 q-rows x (b,h); key blocks of 64. 8 warps (wm 0..3 x wn 0..1).
// ---------------------------------------------------------------------------
constexpr int ASK  = 72;
constexpr int APL  = 64 * ASK;
// planes: Qh Ql Ph Pl + 2 stages x (Kh Kl Vh Vl) = 12 planes
constexpr int ATTN_SMEM_BYTES = 12 * APL * 2 + 4 * 64 * 4;   // 111616

__global__ __launch_bounds__(256, 2) void attn_tc_kernel(
    const bf16* __restrict__ Qh_g, const bf16* __restrict__ Ql_g,
    const bf16* __restrict__ Kh_g, const bf16* __restrict__ Kl_g,
    const bf16* __restrict__ Vh_g, const bf16* __restrict__ Vl_g,
    bf16* __restrict__ Oh_g, bf16* __restrict__ Ol_g)
{
    extern __shared__ __align__(16) char smraw[];
    bf16* Qh = (bf16*)smraw;
    bf16* Ql = Qh + APL;
    bf16* Ph = Ql + APL;
    bf16* Pl = Ph + APL;
    bf16* KV = Pl + APL;                  // 2 stages x 4 planes
    float* pmax = (float*)(KV + 8 * APL); // [2][64]
    float* psum = pmax + 2 * 64;          // [2][64]

    const int t    = threadIdx.x;
    const int lane = t & 31;
    const int wid  = t >> 5;
    const int wm   = wid >> 1;
    const int wn   = wid & 1;
    const int bh   = blockIdx.y;
    const int b    = bh / H;
    const int h    = bh % H;
    const int q0   = blockIdx.x * 64;

    const size_t rowBase = ((size_t)b * S + q0) * D + h * HD;
    const size_t kvBase  = ((size_t)b * S) * D + h * HD;

    auto load_kv = [&](int st, int kb) {
        bf16* base = KV + st * 4 * APL;
        #pragma unroll
        for (int i = 0; i < 2; i++) {
            int f   = t + i * 256;
            int rr  = f >> 3;
            int ce  = (f & 7) * 8;
            size_t g = kvBase + (size_t)(kb + rr) * D + ce;
            cpasync16(smem_u32(base + 0 * APL + rr * ASK + ce), Kh_g + g);
            cpasync16(smem_u32(base + 1 * APL + rr * ASK + ce), Kl_g + g);
            cpasync16(smem_u32(base + 2 * APL + rr * ASK + ce), Vh_g + g);
            cpasync16(smem_u32(base + 3 * APL + rr * ASK + ce), Vl_g + g);
        }
        cpcommit();
    };

    // Q loads (own group), then prefetch first two K/V stages
    #pragma unroll
    for (int i = 0; i < 2; i++) {
        int f   = t + i * 256;
        int rr  = f >> 3;
        int ce  = (f & 7) * 8;
        size_t g = rowBase + (size_t)rr * D + ce;
        cpasync16(smem_u32(Qh + rr * ASK + ce), Qh_g + g);
        cpasync16(smem_u32(Ql + rr * ASK + ce), Ql_g + g);
    }
    cpcommit();
    load_kv(0, 0);
    load_kv(1, 64);

    const int r  = wm * 16 + (lane >> 2);
    float m0 = -1e30f, m8 = -1e30f, l0 = 0.f, l8 = 0.f;
    float acc_o[4][4];
    #pragma unroll
    for (int i = 0; i < 4; i++)
        #pragma unroll
        for (int j = 0; j < 4; j++) acc_o[i][j] = 0.f;

    for (int kb = 0; kb < S; kb += 64) {
        const int st = (kb >> 6) & 1;
        bf16* Kh = KV + st * 4 * APL;
        bf16* Kl = Kh + APL;
        bf16* Vh = Kl + APL;
        bf16* Vl = Vh + APL;

        // Current stage's group complete; next stage may stay in flight.
        cpwait<1>();
        __syncthreads();

        // ---- S = Q @ K^T ----
        float acc_s[4][4];
        #pragma unroll
        for (int i = 0; i < 4; i++)
            #pragma unroll
            for (int j = 0; j < 4; j++) acc_s[i][j] = 0.f;

        #pragma unroll
        for (int ks = 0; ks < 64; ks += 16) {
            unsigned ah[4], al[4], bhf[4][2], blf[4][2];
            ldmx4(ah, addrA<ASK>(Qh, wm * 16, ks, lane));
            ldmx4(al, addrA<ASK>(Ql, wm * 16, ks, lane));
            #pragma unroll
            for (int nt = 0; nt < 2; nt++) {
                ldmx4(&bhf[nt * 2][0], addrB<ASK>(Kh, wn * 32 + nt * 16, ks, lane));
                ldmx4(&blf[nt * 2][0], addrB<ASK>(Kl, wn * 32 + nt * 16, ks, lane));
            }
            #pragma unroll
            for (int ns = 0; ns < 4; ns++) {
                mma16816(acc_s[ns], ah, bhf[ns]);
                mma16816(acc_s[ns], ah, blf[ns]);
                mma16816(acc_s[ns], al, bhf[ns]);
            }
        }

        #pragma unroll
        for (int ns = 0; ns < 4; ns++)
            #pragma unroll
            for (int j = 0; j < 4; j++) acc_s[ns][j] *= 0.125f;

        float pm0 = -1e30f, pm8 = -1e30f;
        #pragma unroll
        for (int ns = 0; ns < 4; ns++) {
            pm0 = fmaxf(pm0, fmaxf(acc_s[ns][0], acc_s[ns][1]));
            pm8 = fmaxf(pm8, fmaxf(acc_s[ns][2], acc_s[ns][3]));
        }
        pm0 = fmaxf(pm0, __shfl_xor_sync(0xffffffffu, pm0, 1));
        pm0 = fmaxf(pm0, __shfl_xor_sync(0xffffffffu, pm0, 2));
        pm8 = fmaxf(pm8, __shfl_xor_sync(0xffffffffu, pm8, 1));
        pm8 = fmaxf(pm8, __shfl_xor_sync(0xffffffffu, pm8, 2));
        if ((lane & 3) == 0) {
            pmax[wn * 64 + r]     = pm0;
            pmax[wn * 64 + r + 8] = pm8;
        }
        __syncthreads();

        float mnew0 = fmaxf(m0, fmaxf(pmax[r],     pmax[64 + r]));
        float mnew8 = fmaxf(m8, fmaxf(pmax[r + 8], pmax[64 + r + 8]));
        float alpha0 = __expf(m0 - mnew0);
        float alpha8 = __expf(m8 - mnew8);

        float ps0 = 0.f, ps8 = 0.f;
        #pragma unroll
        for (int ns = 0; ns < 4; ns++) {
            int c = wn * 32 + ns * 8 + (lane & 3) * 2;
            float p00 = __expf(acc_s[ns][0] - mnew0);
            float p01 = __expf(acc_s[ns][1] - mnew0);
            float p10 = __expf(acc_s[ns][2] - mnew8);
            float p11 = __expf(acc_s[ns][3] - mnew8);
            ps0 += p00 + p01;
            ps8 += p10 + p11;
            bf16 h0, lo0, h1, lo1;
            split_bf16(p00, h0, lo0); split_bf16(p01, h1, lo1);
            *(unsigned*)(Ph + r * ASK + c) = pack2(h0, h1);
            *(unsigned*)(Pl + r * ASK + c) = pack2(lo0, lo1);
            split_bf16(p10, h0, lo0); split_bf16(p11, h1, lo1);
            *(unsigned*)(Ph + (r + 8) * ASK + c) = pack2(h0, h1);
            *(unsigned*)(Pl + (r + 8) * ASK + c) = pack2(lo0, lo1);
            acc_o[ns][0] *= alpha0; acc_o[ns][1] *= alpha0;
            acc_o[ns][2] *= alpha8; acc_o[ns][3] *= alpha8;
        }
        ps0 += __shfl_xor_sync(0xffffffffu, ps0, 1);
        ps0 += __shfl_xor_sync(0xffffffffu, ps0, 2);
        ps8 += __shfl_xor_sync(0xffffffffu, ps8, 1);
        ps8 += __shfl_xor_sync(0xffffffffu, ps8, 2);
        if ((lane & 3) == 0) {
            psum[wn * 64 + r]     = ps0;
            psum[wn * 64 + r + 8] = ps8;
        }
        __syncthreads();

        l0 = l0 * alpha0 + psum[r]     + psum[64 + r];
        l8 = l8 * alpha8 + psum[r + 8] + psum[64 + r + 8];
        m0 = mnew0; m8 = mnew8;

        // ---- O += P @ V (V^T via ldmatrix.trans) ----
        #pragma unroll
        for (int ks = 0; ks < 64; ks += 16) {
            unsigned ah[4], al[4], bhf[4][2], blf[4][2];
            ldmx4(ah, addrA<ASK>(Ph, wm * 16, ks, lane));
            ldmx4(al, addrA<ASK>(Pl, wm * 16, ks, lane));
            #pragma unroll
            for (int nt = 0; nt < 2; nt++) {
                ldmx4t(&bhf[nt * 2][0], addrBT<ASK>(Vh, ks, wn * 32 + nt * 16, lane));
                ldmx4t(&blf[nt * 2][0], addrBT<ASK>(Vl, ks, wn * 32 + nt * 16, lane));
            }
            #pragma unroll
            for (int ns = 0; ns < 4; ns++) {
                mma16816(acc_o[ns], ah, bhf[ns]);
                mma16816(acc_o[ns], ah, blf[ns]);
                mma16816(acc_o[ns], al, bhf[ns]);
            }
        }

        // All warps done reading stage st; refill it with kb+128 (or commit
        // an empty group to keep the one-group-per-iteration cadence that
        // cpwait<1> relies on).
        __syncthreads();
        if (kb + 128 < S) load_kv(st, kb + 128);
        else              cpcommit();
    }

    {
        float inv0 = 1.0f / l0;
        float inv8 = 1.0f / l8;
        size_t row = (size_t)b * S + q0 + r;
        #pragma unroll
        for (int ns = 0; ns < 4; ns++) {
            int col = h * HD + wn * 32 + ns * 8 + (lane & 3) * 2;
            float v00 = acc_o[ns][0] * inv0, v01 = acc_o[ns][1] * inv0;
            float v10 = acc_o[ns][2] * inv8, v11 = acc_o[ns][3] * inv8;
            bf16 h0, lo0, h1, lo1;
            split_bf16(v00, h0, lo0); split_bf16(v01, h1, lo1);
            *(unsigned*)(Oh_g + row * D + col) = pack2(h0, h1);
            *(unsigned*)(Ol_g + row * D + col) = pack2(lo0, lo1);
            split_bf16(v10, h0, lo0); split_bf16(v11, h1, lo1);
            *(unsigned*)(Oh_g + (row + 8) * D + col) = pack2(h0, h1);
            *(unsigned*)(Ol_g + (row + 8) * D + col) = pack2(lo0, lo1);
        }
    }
}

// ---------------------------------------------------------------------------
// Launch
// ---------------------------------------------------------------------------
extern "C" void kernel_launch(void* const* d_in, const int* in_sizes, int n_in,
                              void* d_out, int out_size)
{
    const float* x  = (const float*)d_in[0];
    const float* Wq = (const float*)d_in[1];
    const float* bq = (const float*)d_in[2];
    const float* Wk = (const float*)d_in[3];
    const float* bk = (const float*)d_in[4];
    const float* Wv = (const float*)d_in[5];
    const float* bv = (const float*)d_in[6];
    const float* Wo = (const float*)d_in[7];
    const float* bo = (const float*)d_in[8];
    float* out = (float*)d_out;

    bf16 *xh, *xl, *Qh, *Ql, *Kh, *Kl, *Vh, *Vl, *Oh, *Ol, *WTh, *WTl;
    cudaGetSymbolAddress((void**)&xh, g_xh);
    cudaGetSymbolAddress((void**)&xl, g_xl);
    cudaGetSymbolAddress((void**)&Qh, g_Qh);
    cudaGetSymbolAddress((void**)&Ql, g_Ql);
    cudaGetSymbolAddress((void**)&Kh, g_Kh);
    cudaGetSymbolAddress((void**)&Kl, g_Kl);
    cudaGetSymbolAddress((void**)&Vh, g_Vh);
    cudaGetSymbolAddress((void**)&Vl, g_Vl);
    cudaGetSymbolAddress((void**)&Oh, g_Oh);
    cudaGetSymbolAddress((void**)&Ol, g_Ol);
    cudaGetSymbolAddress((void**)&WTh, g_WTh);
    cudaGetSymbolAddress((void**)&WTl, g_WTl);
    const size_t WSZ = (size_t)D * D;

    cudaFuncSetAttribute(qkv_gemm_kernel, cudaFuncAttributeMaxDynamicSharedMemorySize,
                         GEMM_SMEM_BYTES);
    cudaFuncSetAttribute(oproj_gemm_kernel, cudaFuncAttributeMaxDynamicSharedMemorySize,
                         GEMM_SMEM_BYTES);
    cudaFuncSetAttribute(attn_tc_kernel, cudaFuncAttributeMaxDynamicSharedMemorySize,
                         ATTN_SMEM_BYTES);

    // Prep: split x; transpose-split all 4 weights in one launch.
    xprep_kernel<<<(M * D) / 1024, 256>>>(x, xh, xl);
    WPrepPtrs wp;
    wp.W[0] = Wq; wp.Th[0] = WTh + 0 * WSZ; wp.Tl[0] = WTl + 0 * WSZ;
    wp.W[1] = Wk; wp.Th[1] = WTh + 1 * WSZ; wp.Tl[1] = WTl + 1 * WSZ;
    wp.W[2] = Wv; wp.Th[2] = WTh + 2 * WSZ; wp.Tl[2] = WTl + 2 * WSZ;
    wp.W[3] = Wo; wp.Th[3] = WTh + 3 * WSZ; wp.Tl[3] = WTl + 3 * WSZ;
    wprep_kernel<<<dim3(D / 32, D / 32, 4), dim3(32, 8)>>>(wp);

    // Fused Q/K/V projections (one launch, grid.z = 3)
    QKVParams qp;
    qp.Wh[0] = WTh + 0 * WSZ; qp.Wl[0] = WTl + 0 * WSZ; qp.bias[0] = bq;
    qp.Ch[0] = Qh; qp.Cl[0] = Ql;
    qp.Wh[1] = WTh + 1 * WSZ; qp.Wl[1] = WTl + 1 * WSZ; qp.bias[1] = bk;
    qp.Ch[1] = Kh; qp.Cl[1] = Kl;
    qp.Wh[2] = WTh + 2 * WSZ; qp.Wl[2] = WTl + 2 * WSZ; qp.bias[2] = bv;
    qp.Ch[2] = Vh; qp.Cl[2] = Vl;
    qkv_gemm_kernel<<<dim3(D / 128, M / 128, 3), 256, GEMM_SMEM_BYTES>>>(xh, xl, qp);

    // Attention -> split-bf16 O planes
    attn_tc_kernel<<<dim3(S / 64, B * H), 256, ATTN_SMEM_BYTES>>>(
        Qh, Ql, Kh, Kl, Vh, Vl, Oh, Ol);

    // Output projection -> fp32 out
    oproj_gemm_kernel<<<dim3(D / 128, M / 128), 256, GEMM_SMEM_BYTES>>>(
        Oh, Ol, WTh + 3 * WSZ, WTl + 3 * WSZ, bo, out);
}

// round 11
// speedup vs baseline: 1.1505x; 1.1505x over previous
#include <cuda_runtime.h>
#include <cuda_bf16.h>
#include <stdint.h>
#include <math.h>

// Problem constants
constexpr int B  = 2;
constexpr int S  = 2048;
constexpr int D  = 1024;
constexpr int H  = 16;
constexpr int HD = 64;
constexpr int M  = B * S;          // 4096 rows
static_assert(H * HD == D, "");

typedef __nv_bfloat16 bf16;

// ---------------------------------------------------------------------------
// Persistent split-bf16 planes (static device globals — allocation-free)
// ---------------------------------------------------------------------------
__device__ bf16 g_xh[(size_t)M * D], g_xl[(size_t)M * D];
__device__ bf16 g_Qh[(size_t)M * D], g_Ql[(size_t)M * D];
__device__ bf16 g_Kh[(size_t)M * D], g_Kl[(size_t)M * D];
__device__ bf16 g_Vh[(size_t)M * D], g_Vl[(size_t)M * D];
__device__ bf16 g_Oh[(size_t)M * D], g_Ol[(size_t)M * D];
__device__ bf16 g_WTh[4][(size_t)D * D], g_WTl[4][(size_t)D * D];  // [n][k]

// ---------------------------------------------------------------------------
// Helpers
// ---------------------------------------------------------------------------
__device__ __forceinline__ void split_bf16(float x, bf16& h, bf16& l) {
    h = __float2bfloat16(x);
    l = __float2bfloat16(x - __bfloat162float(h));
}
__device__ __forceinline__ unsigned pack2(bf16 a, bf16 b) {
    __nv_bfloat162 p; p.x = a; p.y = b;
    return *(unsigned*)&p;
}
// Pack hi parts of two floats into bf16x2; return lo-parts packed as well.
__device__ __forceinline__ void split_pack2(float a, float b, unsigned& hi, unsigned& lo) {
    bf16 ha, la, hb, lb;
    split_bf16(a, ha, la);
    split_bf16(b, hb, lb);
    hi = pack2(ha, hb);
    lo = pack2(la, lb);
}
__device__ __forceinline__ uint32_t smem_u32(const void* p) {
    return (uint32_t)__cvta_generic_to_shared(p);
}
__device__ __forceinline__ void cpasync16(uint32_t dst, const void* src) {
    asm volatile("cp.async.cg.shared.global [%0], [%1], 16;\n" :: "r"(dst), "l"(src));
}
__device__ __forceinline__ void cpcommit() {
    asm volatile("cp.async.commit_group;\n");
}
template <int N>
__device__ __forceinline__ void cpwait() {
    asm volatile("cp.async.wait_group %0;\n" :: "n"(N));
}

// D += A(16x16) * B(16x8), bf16 in, fp32 acc.
__device__ __forceinline__ void mma16816(float* c, const unsigned* a, const unsigned* b) {
    asm volatile(
        "mma.sync.aligned.m16n8k16.row.col.f32.bf16.bf16.f32 "
        "{%0,%1,%2,%3},{%4,%5,%6,%7},{%8,%9},{%0,%1,%2,%3};\n"
        : "+f"(c[0]), "+f"(c[1]), "+f"(c[2]), "+f"(c[3])
        : "r"(a[0]), "r"(a[1]), "r"(a[2]), "r"(a[3]), "r"(b[0]), "r"(b[1]));
}
__device__ __forceinline__ void ldmx4(unsigned* r, uint32_t addr) {
    asm volatile("ldmatrix.sync.aligned.m8n8.x4.shared.b16 {%0,%1,%2,%3}, [%4];\n"
                 : "=r"(r[0]), "=r"(r[1]), "=r"(r[2]), "=r"(r[3]) : "r"(addr));
}
__device__ __forceinline__ void ldmx4t(unsigned* r, uint32_t addr) {
    asm volatile("ldmatrix.sync.aligned.m8n8.x4.trans.shared.b16 {%0,%1,%2,%3}, [%4];\n"
                 : "=r"(r[0]), "=r"(r[1]), "=r"(r[2]), "=r"(r[3]) : "r"(addr));
}
template <int SK>
__device__ __forceinline__ uint32_t addrA(const bf16* base, int row0, int k0, int lane) {
    int g = lane >> 3, lr = lane & 7;
    return smem_u32(base + (row0 + (g & 1) * 8 + lr) * SK + k0 + (g >> 1) * 8);
}
template <int SK>
__device__ __forceinline__ uint32_t addrB(const bf16* base, int n0, int k0, int lane) {
    int g = lane >> 3, lr = lane & 7;
    return smem_u32(base + (n0 + (g >> 1) * 8 + lr) * SK + k0 + (g & 1) * 8);
}
template <int SK>
__device__ __forceinline__ uint32_t addrBT(const bf16* base, int kk0, int d0, int lane) {
    int g = lane >> 3, lr = lane & 7;
    return smem_u32(base + (kk0 + (g & 1) * 8 + lr) * SK + d0 + (g >> 1) * 8);
}

// ---------------------------------------------------------------------------
// Prep 1: split x into hi/lo bf16 planes.
// ---------------------------------------------------------------------------
__global__ __launch_bounds__(256) void xprep_kernel(const float* __restrict__ x,
                                                    bf16* __restrict__ xh,
                                                    bf16* __restrict__ xl) {
    size_t i4 = (size_t)blockIdx.x * 256 + threadIdx.x;
    float4 v = *(const float4*)(x + i4 * 4);
    bf16 h0, l0, h1, l1, h2, l2, h3, l3;
    split_bf16(v.x, h0, l0); split_bf16(v.y, h1, l1);
    split_bf16(v.z, h2, l2); split_bf16(v.w, h3, l3);
    *(uint2*)(xh + i4 * 4) = make_uint2(pack2(h0, h1), pack2(h2, h3));
    *(uint2*)(xl + i4 * 4) = make_uint2(pack2(l0, l1), pack2(l2, l3));
}

// ---------------------------------------------------------------------------
// Prep 2: transpose-split W [K][N] -> Th/Tl [N][K].
// ---------------------------------------------------------------------------
__global__ __launch_bounds__(256) void wprep_kernel(const float* __restrict__ W,
                                                    bf16* __restrict__ Th,
                                                    bf16* __restrict__ Tl) {
    __shared__ float tile[32][33];
    int n0 = blockIdx.x * 32, k0 = blockIdx.y * 32;
    int tx = threadIdx.x, ty = threadIdx.y;   // 32 x 8
    #pragma unroll
    for (int j = 0; j < 4; j++)
        tile[ty + j * 8][tx] = W[(size_t)(k0 + ty + j * 8) * D + n0 + tx];
    __syncthreads();
    #pragma unroll
    for (int j = 0; j < 4; j++) {
        int nn = ty + j * 8;
        float v = tile[tx][nn];
        bf16 h, l;
        split_bf16(v, h, l);
        Th[(size_t)(n0 + nn) * D + k0 + tx] = h;
        Tl[(size_t)(n0 + nn) * D + k0 + tx] = l;
    }
}

// ---------------------------------------------------------------------------
// Split-bf16 tensor-core GEMM (exact R7 config — proven).
// C[M,N] = A[M,K] @ B^T[N,K] + bias.  128x128 tile, BK=32, 8 warps (4x2),
// cp.async double-buffered.
// ---------------------------------------------------------------------------
constexpr int GSK   = 40;                       // smem k-stride (32 + 8 pad)
constexpr int GPL   = 128 * GSK;                // plane elems
constexpr int GSTG  = 4 * GPL;                  // stage elems (Ah Al Bh Bl)
constexpr int GEMM_SMEM_BYTES = 2 * GSTG * 2;   // 2 stages * bf16

__global__ __launch_bounds__(256) void gemm_tc(
    const bf16* __restrict__ Ah_g, const bf16* __restrict__ Al_g,
    const bf16* __restrict__ Bh_g, const bf16* __restrict__ Bl_g,
    const float* __restrict__ bias,
    float* __restrict__ Cf, bf16* __restrict__ Ch, bf16* __restrict__ Cl)
{
    extern __shared__ __align__(16) char smraw[];
    bf16* sm = (bf16*)smraw;

    const int t    = threadIdx.x;
    const int lane = t & 31;
    const int wid  = t >> 5;
    const int wm   = wid >> 1;       // 0..3
    const int wn   = wid & 1;        // 0..1
    const int m0   = blockIdx.y * 128;
    const int n0   = blockIdx.x * 128;
    constexpr int NIT = D / 32;      // 32

    float acc[2][8][4];
    #pragma unroll
    for (int i = 0; i < 2; i++)
        #pragma unroll
        for (int j = 0; j < 8; j++)
            #pragma unroll
            for (int c = 0; c < 4; c++) acc[i][j][c] = 0.f;

    auto load_stage = [&](int st, int k0) {
        bf16* sAh = sm + st * GSTG;
        bf16* sAl = sAh + GPL;
        bf16* sBh = sAl + GPL;
        bf16* sBl = sBh + GPL;
        #pragma unroll
        for (int i = 0; i < 2; i++) {
            int f   = t + i * 256;         // 0..511
            int row = f >> 2;              // 0..127
            int ce  = (f & 3) * 8;         // k elem offset (16B chunks)
            size_t ga = (size_t)(m0 + row) * D + k0 + ce;
            size_t gb = (size_t)(n0 + row) * D + k0 + ce;
            cpasync16(smem_u32(sAh + row * GSK + ce), Ah_g + ga);
            cpasync16(smem_u32(sAl + row * GSK + ce), Al_g + ga);
            cpasync16(smem_u32(sBh + row * GSK + ce), Bh_g + gb);
            cpasync16(smem_u32(sBl + row * GSK + ce), Bl_g + gb);
        }
        cpcommit();
    };

    load_stage(0, 0);
    int st = 0;
    for (int it = 0; it < NIT; it++) {
        if (it + 1 < NIT) { load_stage(st ^ 1, (it + 1) * 32); cpwait<1>(); }
        else             { cpwait<0>(); }
        __syncthreads();

        bf16* sAh = sm + st * GSTG;
        bf16* sAl = sAh + GPL;
        bf16* sBh = sAl + GPL;
        bf16* sBl = sBh + GPL;

        #pragma unroll
        for (int ks = 0; ks < 32; ks += 16) {
            unsigned bh[8][2], bl[8][2];
            #pragma unroll
            for (int nt = 0; nt < 4; nt++) {
                ldmx4(&bh[nt * 2][0], addrB<GSK>(sBh, wn * 64 + nt * 16, ks, lane));
                ldmx4(&bl[nt * 2][0], addrB<GSK>(sBl, wn * 64 + nt * 16, ks, lane));
            }
            #pragma unroll
            for (int ms = 0; ms < 2; ms++) {
                unsigned ah[4], al[4];
                ldmx4(ah, addrA<GSK>(sAh, wm * 32 + ms * 16, ks, lane));
                ldmx4(al, addrA<GSK>(sAl, wm * 32 + ms * 16, ks, lane));
                #pragma unroll
                for (int ns = 0; ns < 8; ns++) {
                    mma16816(acc[ms][ns], ah, bh[ns]);
                    mma16816(acc[ms][ns], ah, bl[ns]);
                    mma16816(acc[ms][ns], al, bh[ns]);
                }
            }
        }
        __syncthreads();
        st ^= 1;
    }

    // Epilogue
    #pragma unroll
    for (int ms = 0; ms < 2; ms++) {
        int row = m0 + wm * 32 + ms * 16 + (lane >> 2);
        #pragma unroll
        for (int ns = 0; ns < 8; ns++) {
            int col = n0 + wn * 64 + ns * 8 + (lane & 3) * 2;
            float b0 = bias[col], b1 = bias[col + 1];
            float v00 = acc[ms][ns][0] + b0, v01 = acc[ms][ns][1] + b1;
            float v10 = acc[ms][ns][2] + b0, v11 = acc[ms][ns][3] + b1;
            if (Cf) {
                *(float2*)(Cf + (size_t)row * D + col)       = make_float2(v00, v01);
                *(float2*)(Cf + (size_t)(row + 8) * D + col) = make_float2(v10, v11);
            } else {
                bf16 h0, l0, h1, l1;
                split_bf16(v00, h0, l0); split_bf16(v01, h1, l1);
                *(unsigned*)(Ch + (size_t)row * D + col) = pack2(h0, h1);
                *(unsigned*)(Cl + (size_t)row * D + col) = pack2(l0, l1);
                split_bf16(v10, h0, l0); split_bf16(v11, h1, l1);
                *(unsigned*)(Ch + (size_t)(row + 8) * D + col) = pack2(h0, h1);
                *(unsigned*)(Cl + (size_t)(row + 8) * D + col) = pack2(l0, l1);
            }
        }
    }
}

// ---------------------------------------------------------------------------
// Split-bf16 HMMA flash attention, WARP-LOCAL softmax + register-resident P.
// CTA = 64 q-rows x (b,h), 128 threads = 4 warps; each warp owns 16 q-rows
// and the FULL 64-key block (S) / full 64-d output (P@V).
// P never touches smem: acc_s C-fragments are re-packed in registers into
// split-bf16 A-fragments for the P@V MMAs (C-layout == A-layout trick).
// K/V double-buffered via cp.async.
// ---------------------------------------------------------------------------
constexpr int ASK  = 72;                 // plane stride (64 + 8)
constexpr int APL  = 64 * ASK;           // plane elems
// planes: Qh Ql + 2 stages x (Kh Kl Vh Vl) = 10 planes
constexpr int ATTN_SMEM_BYTES = 10 * APL * 2;   // 92160

__global__ __launch_bounds__(128, 2) void attn_tc_kernel(
    const bf16* __restrict__ Qh_g, const bf16* __restrict__ Ql_g,
    const bf16* __restrict__ Kh_g, const bf16* __restrict__ Kl_g,
    const bf16* __restrict__ Vh_g, const bf16* __restrict__ Vl_g,
    bf16* __restrict__ Oh_g, bf16* __restrict__ Ol_g)
{
    extern __shared__ __align__(16) char smraw[];
    bf16* Qh = (bf16*)smraw;
    bf16* Ql = Qh + APL;
    bf16* KV = Ql + APL;     // 2 stages x {Kh, Kl, Vh, Vl}

    const int t    = threadIdx.x;
    const int lane = t & 31;
    const int wm   = t >> 5;       // warp 0..3 — owns q rows [wm*16, wm*16+16)
    const int bh   = blockIdx.y;
    const int b    = bh / H;
    const int h    = bh % H;
    const int q0   = blockIdx.x * 64;

    const size_t rowBase = ((size_t)b * S + q0) * D + h * HD;
    const size_t kvBase  = ((size_t)b * S) * D + h * HD;

    auto load_kv = [&](int st, int kb) {
        bf16* base = KV + st * 4 * APL;
        #pragma unroll
        for (int i = 0; i < 4; i++) {
            int f   = t + i * 128;        // 0..511
            int rr  = f >> 3;             // 0..63
            int ce  = (f & 7) * 8;        // 0..56
            size_t g = kvBase + (size_t)(kb + rr) * D + ce;
            cpasync16(smem_u32(base + 0 * APL + rr * ASK + ce), Kh_g + g);
            cpasync16(smem_u32(base + 1 * APL + rr * ASK + ce), Kl_g + g);
            cpasync16(smem_u32(base + 2 * APL + rr * ASK + ce), Vh_g + g);
            cpasync16(smem_u32(base + 3 * APL + rr * ASK + ce), Vl_g + g);
        }
        cpcommit();
    };

    // Q loads (own group), then prefetch two K/V stages.
    #pragma unroll
    for (int i = 0; i < 4; i++) {
        int f   = t + i * 128;
        int rr  = f >> 3;
        int ce  = (f & 7) * 8;
        size_t g = rowBase + (size_t)rr * D + ce;
        cpasync16(smem_u32(Qh + rr * ASK + ce), Qh_g + g);
        cpasync16(smem_u32(Ql + rr * ASK + ce), Ql_g + g);
    }
    cpcommit();
    load_kv(0, 0);
    load_kv(1, 64);

    const int r = wm * 16 + (lane >> 2);   // this thread's first q-row
    float m0 = -1e30f, m8 = -1e30f, l0 = 0.f, l8 = 0.f;
    float acc_o[8][4];
    #pragma unroll
    for (int i = 0; i < 8; i++)
        #pragma unroll
        for (int j = 0; j < 4; j++) acc_o[i][j] = 0.f;

    for (int kb = 0; kb < S; kb += 64) {
        const int st = (kb >> 6) & 1;
        bf16* Kh = KV + st * 4 * APL;
        bf16* Kl = Kh + APL;
        bf16* Vh = Kl + APL;
        bf16* Vl = Vh + APL;

        cpwait<1>();     // current stage complete; next may be in flight
        __syncthreads();

        // ---- S = Q @ K^T : warp tile 16 q x 64 keys ----
        float acc_s[8][4];
        #pragma unroll
        for (int i = 0; i < 8; i++)
            #pragma unroll
            for (int j = 0; j < 4; j++) acc_s[i][j] = 0.f;

        #pragma unroll
        for (int ks = 0; ks < 64; ks += 16) {
            unsigned ah[4], al[4], bhf[8][2], blf[8][2];
            ldmx4(ah, addrA<ASK>(Qh, wm * 16, ks, lane));
            ldmx4(al, addrA<ASK>(Ql, wm * 16, ks, lane));
            #pragma unroll
            for (int nt = 0; nt < 4; nt++) {
                ldmx4(&bhf[nt * 2][0], addrB<ASK>(Kh, nt * 16, ks, lane));
                ldmx4(&blf[nt * 2][0], addrB<ASK>(Kl, nt * 16, ks, lane));
            }
            #pragma unroll
            for (int ns = 0; ns < 8; ns++) {
                mma16816(acc_s[ns], ah, bhf[ns]);
                mma16816(acc_s[ns], ah, blf[ns]);
                mma16816(acc_s[ns], al, bhf[ns]);
            }
        }

        // ---- warp-local online softmax (rows r, r+8) ----
        #pragma unroll
        for (int ns = 0; ns < 8; ns++)
            #pragma unroll
            for (int j = 0; j < 4; j++) acc_s[ns][j] *= 0.125f;

        float pm0 = -1e30f, pm8 = -1e30f;
        #pragma unroll
        for (int ns = 0; ns < 8; ns++) {
            pm0 = fmaxf(pm0, fmaxf(acc_s[ns][0], acc_s[ns][1]));
            pm8 = fmaxf(pm8, fmaxf(acc_s[ns][2], acc_s[ns][3]));
        }
        pm0 = fmaxf(pm0, __shfl_xor_sync(0xffffffffu, pm0, 1));
        pm0 = fmaxf(pm0, __shfl_xor_sync(0xffffffffu, pm0, 2));
        pm8 = fmaxf(pm8, __shfl_xor_sync(0xffffffffu, pm8, 1));
        pm8 = fmaxf(pm8, __shfl_xor_sync(0xffffffffu, pm8, 2));

        float mnew0 = fmaxf(m0, pm0);
        float mnew8 = fmaxf(m8, pm8);
        float alpha0 = __expf(m0 - mnew0);
        float alpha8 = __expf(m8 - mnew8);

        float ps0 = 0.f, ps8 = 0.f;
        #pragma unroll
        for (int ns = 0; ns < 8; ns++) {
            acc_s[ns][0] = __expf(acc_s[ns][0] - mnew0);
            acc_s[ns][1] = __expf(acc_s[ns][1] - mnew0);
            acc_s[ns][2] = __expf(acc_s[ns][2] - mnew8);
            acc_s[ns][3] = __expf(acc_s[ns][3] - mnew8);
            ps0 += acc_s[ns][0] + acc_s[ns][1];
            ps8 += acc_s[ns][2] + acc_s[ns][3];
        }
        ps0 += __shfl_xor_sync(0xffffffffu, ps0, 1);
        ps0 += __shfl_xor_sync(0xffffffffu, ps0, 2);
        ps8 += __shfl_xor_sync(0xffffffffu, ps8, 1);
        ps8 += __shfl_xor_sync(0xffffffffu, ps8, 2);

        l0 = l0 * alpha0 + ps0;
        l8 = l8 * alpha8 + ps8;
        m0 = mnew0; m8 = mnew8;

        // ---- pack P into split-bf16 A-fragments IN REGISTERS ----
        // A-frag for key-chunk kk: a0=(r,k), a1=(r+8,k), a2=(r,k+8), a3=(r+8,k+8);
        // C-layout of acc_s matches lane-for-lane: n-tile 2kk gives k..k+7, 2kk+1 gives k+8..k+15.
        unsigned pa_h[4][4], pa_l[4][4];
        #pragma unroll
        for (int kk = 0; kk < 4; kk++) {
            split_pack2(acc_s[2 * kk][0],     acc_s[2 * kk][1],     pa_h[kk][0], pa_l[kk][0]);
            split_pack2(acc_s[2 * kk][2],     acc_s[2 * kk][3],     pa_h[kk][1], pa_l[kk][1]);
            split_pack2(acc_s[2 * kk + 1][0], acc_s[2 * kk + 1][1], pa_h[kk][2], pa_l[kk][2]);
            split_pack2(acc_s[2 * kk + 1][2], acc_s[2 * kk + 1][3], pa_h[kk][3], pa_l[kk][3]);
        }

        // rescale O accumulators
        #pragma unroll
        for (int ns = 0; ns < 8; ns++) {
            acc_o[ns][0] *= alpha0; acc_o[ns][1] *= alpha0;
            acc_o[ns][2] *= alpha8; acc_o[ns][3] *= alpha8;
        }

        // ---- O += P @ V : warp tile 16 q x 64 d (V^T via ldmatrix.trans) ----
        #pragma unroll
        for (int ks = 0; ks < 4; ks++) {
            unsigned bvh[8][2], bvl[8][2];
            #pragma unroll
            for (int nt = 0; nt < 4; nt++) {
                ldmx4t(&bvh[nt * 2][0], addrBT<ASK>(Vh, ks * 16, nt * 16, lane));
                ldmx4t(&bvl[nt * 2][0], addrBT<ASK>(Vl, ks * 16, nt * 16, lane));
            }
            #pragma unroll
            for (int ns = 0; ns < 8; ns++) {
                mma16816(acc_o[ns], pa_h[ks], bvh[ns]);
                mma16816(acc_o[ns], pa_h[ks], bvl[ns]);
                mma16816(acc_o[ns], pa_l[ks], bvh[ns]);
            }
        }

        // All warps done reading stage st; refill with kb+128 (or empty commit
        // to keep the one-group-per-iteration cadence cpwait<1> relies on).
        __syncthreads();
        if (kb + 128 < S) load_kv(st, kb + 128);
        else              cpcommit();
    }

    // Epilogue: normalize, split-store to O planes [M][D]
    {
        float inv0 = 1.0f / l0;
        float inv8 = 1.0f / l8;
        size_t row = (size_t)b * S + q0 + r;
        #pragma unroll
        for (int ns = 0; ns < 8; ns++) {
            int col = h * HD + ns * 8 + (lane & 3) * 2;
            float v00 = acc_o[ns][0] * inv0, v01 = acc_o[ns][1] * inv0;
            float v10 = acc_o[ns][2] * inv8, v11 = acc_o[ns][3] * inv8;
            unsigned hh, ll;
            split_pack2(v00, v01, hh, ll);
            *(unsigned*)(Oh_g + row * D + col) = hh;
            *(unsigned*)(Ol_g + row * D + col) = ll;
            split_pack2(v10, v11, hh, ll);
            *(unsigned*)(Oh_g + (row + 8) * D + col) = hh;
            *(unsigned*)(Ol_g + (row + 8) * D + col) = ll;
        }
    }
}

// ---------------------------------------------------------------------------
// Launch
// ---------------------------------------------------------------------------
extern "C" void kernel_launch(void* const* d_in, const int* in_sizes, int n_in,
                              void* d_out, int out_size)
{
    const float* x  = (const float*)d_in[0];
    const float* Wq = (const float*)d_in[1];
    const float* bq = (const float*)d_in[2];
    const float* Wk = (const float*)d_in[3];
    const float* bk = (const float*)d_in[4];
    const float* Wv = (const float*)d_in[5];
    const float* bv = (const float*)d_in[6];
    const float* Wo = (const float*)d_in[7];
    const float* bo = (const float*)d_in[8];
    float* out = (float*)d_out;

    bf16 *xh, *xl, *Qh, *Ql, *Kh, *Kl, *Vh, *Vl, *Oh, *Ol, *WTh, *WTl;
    cudaGetSymbolAddress((void**)&xh, g_xh);
    cudaGetSymbolAddress((void**)&xl, g_xl);
    cudaGetSymbolAddress((void**)&Qh, g_Qh);
    cudaGetSymbolAddress((void**)&Ql, g_Ql);
    cudaGetSymbolAddress((void**)&Kh, g_Kh);
    cudaGetSymbolAddress((void**)&Kl, g_Kl);
    cudaGetSymbolAddress((void**)&Vh, g_Vh);
    cudaGetSymbolAddress((void**)&Vl, g_Vl);
    cudaGetSymbolAddress((void**)&Oh, g_Oh);
    cudaGetSymbolAddress((void**)&Ol, g_Ol);
    cudaGetSymbolAddress((void**)&WTh, g_WTh);
    cudaGetSymbolAddress((void**)&WTl, g_WTl);
    const size_t WSZ = (size_t)D * D;

    cudaFuncSetAttribute(gemm_tc, cudaFuncAttributeMaxDynamicSharedMemorySize,
                         GEMM_SMEM_BYTES);
    cudaFuncSetAttribute(attn_tc_kernel, cudaFuncAttributeMaxDynamicSharedMemorySize,
                         ATTN_SMEM_BYTES);

    // Prep: split x, transpose-split weights (R7 structure)
    xprep_kernel<<<(M * D) / 1024, 256>>>(x, xh, xl);
    dim3 wgrid(D / 32, D / 32), wblk(32, 8);
    wprep_kernel<<<wgrid, wblk>>>(Wq, WTh + 0 * WSZ, WTl + 0 * WSZ);
    wprep_kernel<<<wgrid, wblk>>>(Wk, WTh + 1 * WSZ, WTl + 1 * WSZ);
    wprep_kernel<<<wgrid, wblk>>>(Wv, WTh + 2 * WSZ, WTl + 2 * WSZ);
    wprep_kernel<<<wgrid, wblk>>>(Wo, WTh + 3 * WSZ, WTl + 3 * WSZ);

    dim3 ggrid(D / 128, M / 128);   // (8, 32)

    // Projections -> split-bf16 Q/K/V planes (separate launches, R7 structure)
    gemm_tc<<<ggrid, 256, GEMM_SMEM_BYTES>>>(xh, xl, WTh + 0 * WSZ, WTl + 0 * WSZ,
                                             bq, nullptr, Qh, Ql);
    gemm_tc<<<ggrid, 256, GEMM_SMEM_BYTES>>>(xh, xl, WTh + 1 * WSZ, WTl + 1 * WSZ,
                                             bk, nullptr, Kh, Kl);
    gemm_tc<<<ggrid, 256, GEMM_SMEM_BYTES>>>(xh, xl, WTh + 2 * WSZ, WTl + 2 * WSZ,
                                             bv, nullptr, Vh, Vl);

    // Attention -> split-bf16 O planes
    attn_tc_kernel<<<dim3(S / 64, B * H), 128, ATTN_SMEM_BYTES>>>(
        Qh, Ql, Kh, Kl, Vh, Vl, Oh, Ol);

    // Output projection -> fp32 out
    gemm_tc<<<ggrid, 256, GEMM_SMEM_BYTES>>>(Oh, Ol, WTh + 3 * WSZ, WTl + 3 * WSZ,
                                             bo, out, nullptr, nullptr);
}

// round 12
// speedup vs baseline: 1.1727x; 1.0192x over previous
#include <cuda_runtime.h>
#include <cuda_bf16.h>
#include <stdint.h>
#include <math.h>

// Problem constants
constexpr int B  = 2;
constexpr int S  = 2048;
constexpr int D  = 1024;
constexpr int H  = 16;
constexpr int HD = 64;
constexpr int M  = B * S;          // 4096 rows
static_assert(H * HD == D, "");

typedef __nv_bfloat16 bf16;

// softmax scale folded into Q: 1/sqrt(HD) * log2(e)
#define QSCALE 0.18033688011112042f

// ---------------------------------------------------------------------------
// Persistent split-bf16 planes (static device globals — allocation-free)
// ---------------------------------------------------------------------------
__device__ bf16 g_xh[(size_t)M * D], g_xl[(size_t)M * D];
__device__ bf16 g_Qh[(size_t)M * D], g_Ql[(size_t)M * D];
__device__ bf16 g_Kh[(size_t)M * D], g_Kl[(size_t)M * D];
__device__ bf16 g_Vh[(size_t)M * D], g_Vl[(size_t)M * D];
__device__ bf16 g_Oh[(size_t)M * D], g_Ol[(size_t)M * D];
__device__ bf16 g_WTh[4][(size_t)D * D], g_WTl[4][(size_t)D * D];  // [n][k]

// ---------------------------------------------------------------------------
// Helpers
// ---------------------------------------------------------------------------
__device__ __forceinline__ void split_bf16(float x, bf16& h, bf16& l) {
    h = __float2bfloat16(x);
    l = __float2bfloat16(x - __bfloat162float(h));
}
__device__ __forceinline__ unsigned pack2(bf16 a, bf16 b) {
    __nv_bfloat162 p; p.x = a; p.y = b;
    return *(unsigned*)&p;
}
__device__ __forceinline__ void split_pack2(float a, float b, unsigned& hi, unsigned& lo) {
    bf16 ha, la, hb, lb;
    split_bf16(a, ha, la);
    split_bf16(b, hb, lb);
    hi = pack2(ha, hb);
    lo = pack2(la, lb);
}
__device__ __forceinline__ float ex2(float x) {
    float y;
    asm("ex2.approx.ftz.f32 %0, %1;" : "=f"(y) : "f"(x));
    return y;
}
__device__ __forceinline__ uint32_t smem_u32(const void* p) {
    return (uint32_t)__cvta_generic_to_shared(p);
}
__device__ __forceinline__ void cpasync16(uint32_t dst, const void* src) {
    asm volatile("cp.async.cg.shared.global [%0], [%1], 16;\n" :: "r"(dst), "l"(src));
}
__device__ __forceinline__ void cpcommit() {
    asm volatile("cp.async.commit_group;\n");
}
template <int N>
__device__ __forceinline__ void cpwait() {
    asm volatile("cp.async.wait_group %0;\n" :: "n"(N));
}

// D += A(16x16) * B(16x8), bf16 in, fp32 acc.
__device__ __forceinline__ void mma16816(float* c, const unsigned* a, const unsigned* b) {
    asm volatile(
        "mma.sync.aligned.m16n8k16.row.col.f32.bf16.bf16.f32 "
        "{%0,%1,%2,%3},{%4,%5,%6,%7},{%8,%9},{%0,%1,%2,%3};\n"
        : "+f"(c[0]), "+f"(c[1]), "+f"(c[2]), "+f"(c[3])
        : "r"(a[0]), "r"(a[1]), "r"(a[2]), "r"(a[3]), "r"(b[0]), "r"(b[1]));
}
__device__ __forceinline__ void ldmx4(unsigned* r, uint32_t addr) {
    asm volatile("ldmatrix.sync.aligned.m8n8.x4.shared.b16 {%0,%1,%2,%3}, [%4];\n"
                 : "=r"(r[0]), "=r"(r[1]), "=r"(r[2]), "=r"(r[3]) : "r"(addr));
}
__device__ __forceinline__ void ldmx4t(unsigned* r, uint32_t addr) {
    asm volatile("ldmatrix.sync.aligned.m8n8.x4.trans.shared.b16 {%0,%1,%2,%3}, [%4];\n"
                 : "=r"(r[0]), "=r"(r[1]), "=r"(r[2]), "=r"(r[3]) : "r"(addr));
}
template <int SK>
__device__ __forceinline__ uint32_t addrA(const bf16* base, int row0, int k0, int lane) {
    int g = lane >> 3, lr = lane & 7;
    return smem_u32(base + (row0 + (g & 1) * 8 + lr) * SK + k0 + (g >> 1) * 8);
}
template <int SK>
__device__ __forceinline__ uint32_t addrB(const bf16* base, int n0, int k0, int lane) {
    int g = lane >> 3, lr = lane & 7;
    return smem_u32(base + (n0 + (g >> 1) * 8 + lr) * SK + k0 + (g & 1) * 8);
}
template <int SK>
__device__ __forceinline__ uint32_t addrBT(const bf16* base, int kk0, int d0, int lane) {
    int g = lane >> 3, lr = lane & 7;
    return smem_u32(base + (kk0 + (g & 1) * 8 + lr) * SK + d0 + (g >> 1) * 8);
}

// ---------------------------------------------------------------------------
// Prep 1: split x into hi/lo bf16 planes.
// ---------------------------------------------------------------------------
__global__ __launch_bounds__(256) void xprep_kernel(const float* __restrict__ x,
                                                    bf16* __restrict__ xh,
                                                    bf16* __restrict__ xl) {
    size_t i4 = (size_t)blockIdx.x * 256 + threadIdx.x;
    float4 v = *(const float4*)(x + i4 * 4);
    bf16 h0, l0, h1, l1, h2, l2, h3, l3;
    split_bf16(v.x, h0, l0); split_bf16(v.y, h1, l1);
    split_bf16(v.z, h2, l2); split_bf16(v.w, h3, l3);
    *(uint2*)(xh + i4 * 4) = make_uint2(pack2(h0, h1), pack2(h2, h3));
    *(uint2*)(xl + i4 * 4) = make_uint2(pack2(l0, l1), pack2(l2, l3));
}

// ---------------------------------------------------------------------------
// Prep 2: transpose-split W [K][N] -> Th/Tl [N][K].
// ---------------------------------------------------------------------------
__global__ __launch_bounds__(256) void wprep_kernel(const float* __restrict__ W,
                                                    bf16* __restrict__ Th,
                                                    bf16* __restrict__ Tl) {
    __shared__ float tile[32][33];
    int n0 = blockIdx.x * 32, k0 = blockIdx.y * 32;
    int tx = threadIdx.x, ty = threadIdx.y;   // 32 x 8
    #pragma unroll
    for (int j = 0; j < 4; j++)
        tile[ty + j * 8][tx] = W[(size_t)(k0 + ty + j * 8) * D + n0 + tx];
    __syncthreads();
    #pragma unroll
    for (int j = 0; j < 4; j++) {
        int nn = ty + j * 8;
        float v = tile[tx][nn];
        bf16 h, l;
        split_bf16(v, h, l);
        Th[(size_t)(n0 + nn) * D + k0 + tx] = h;
        Tl[(size_t)(n0 + nn) * D + k0 + tx] = l;
    }
}

// ---------------------------------------------------------------------------
// Split-bf16 tensor-core GEMM (R7/R11 proven config + cscale epilogue).
// C[M,N] = (A[M,K] @ B^T[N,K] + bias) * cscale.
// ---------------------------------------------------------------------------
constexpr int GSK   = 40;                       // smem k-stride (32 + 8 pad)
constexpr int GPL   = 128 * GSK;                // plane elems
constexpr int GSTG  = 4 * GPL;                  // stage elems (Ah Al Bh Bl)
constexpr int GEMM_SMEM_BYTES = 2 * GSTG * 2;   // 2 stages * bf16

__global__ __launch_bounds__(256) void gemm_tc(
    const bf16* __restrict__ Ah_g, const bf16* __restrict__ Al_g,
    const bf16* __restrict__ Bh_g, const bf16* __restrict__ Bl_g,
    const float* __restrict__ bias, float cscale,
    float* __restrict__ Cf, bf16* __restrict__ Ch, bf16* __restrict__ Cl)
{
    extern __shared__ __align__(16) char smraw[];
    bf16* sm = (bf16*)smraw;

    const int t    = threadIdx.x;
    const int lane = t & 31;
    const int wid  = t >> 5;
    const int wm   = wid >> 1;       // 0..3
    const int wn   = wid & 1;        // 0..1
    const int m0   = blockIdx.y * 128;
    const int n0   = blockIdx.x * 128;
    constexpr int NIT = D / 32;      // 32

    float acc[2][8][4];
    #pragma unroll
    for (int i = 0; i < 2; i++)
        #pragma unroll
        for (int j = 0; j < 8; j++)
            #pragma unroll
            for (int c = 0; c < 4; c++) acc[i][j][c] = 0.f;

    auto load_stage = [&](int st, int k0) {
        bf16* sAh = sm + st * GSTG;
        bf16* sAl = sAh + GPL;
        bf16* sBh = sAl + GPL;
        bf16* sBl = sBh + GPL;
        #pragma unroll
        for (int i = 0; i < 2; i++) {
            int f   = t + i * 256;         // 0..511
            int row = f >> 2;              // 0..127
            int ce  = (f & 3) * 8;         // k elem offset (16B chunks)
            size_t ga = (size_t)(m0 + row) * D + k0 + ce;
            size_t gb = (size_t)(n0 + row) * D + k0 + ce;
            cpasync16(smem_u32(sAh + row * GSK + ce), Ah_g + ga);
            cpasync16(smem_u32(sAl + row * GSK + ce), Al_g + ga);
            cpasync16(smem_u32(sBh + row * GSK + ce), Bh_g + gb);
            cpasync16(smem_u32(sBl + row * GSK + ce), Bl_g + gb);
        }
        cpcommit();
    };

    load_stage(0, 0);
    int st = 0;
    for (int it = 0; it < NIT; it++) {
        if (it + 1 < NIT) { load_stage(st ^ 1, (it + 1) * 32); cpwait<1>(); }
        else             { cpwait<0>(); }
        __syncthreads();

        bf16* sAh = sm + st * GSTG;
        bf16* sAl = sAh + GPL;
        bf16* sBh = sAl + GPL;
        bf16* sBl = sBh + GPL;

        #pragma unroll
        for (int ks = 0; ks < 32; ks += 16) {
            unsigned bh[8][2], bl[8][2];
            #pragma unroll
            for (int nt = 0; nt < 4; nt++) {
                ldmx4(&bh[nt * 2][0], addrB<GSK>(sBh, wn * 64 + nt * 16, ks, lane));
                ldmx4(&bl[nt * 2][0], addrB<GSK>(sBl, wn * 64 + nt * 16, ks, lane));
            }
            #pragma unroll
            for (int ms = 0; ms < 2; ms++) {
                unsigned ah[4], al[4];
                ldmx4(ah, addrA<GSK>(sAh, wm * 32 + ms * 16, ks, lane));
                ldmx4(al, addrA<GSK>(sAl, wm * 32 + ms * 16, ks, lane));
                #pragma unroll
                for (int ns = 0; ns < 8; ns++) {
                    mma16816(acc[ms][ns], ah, bh[ns]);
                    mma16816(acc[ms][ns], ah, bl[ns]);
                    mma16816(acc[ms][ns], al, bh[ns]);
                }
            }
        }
        __syncthreads();
        st ^= 1;
    }

    // Epilogue
    #pragma unroll
    for (int ms = 0; ms < 2; ms++) {
        int row = m0 + wm * 32 + ms * 16 + (lane >> 2);
        #pragma unroll
        for (int ns = 0; ns < 8; ns++) {
            int col = n0 + wn * 64 + ns * 8 + (lane & 3) * 2;
            float b0 = bias[col], b1 = bias[col + 1];
            float v00 = (acc[ms][ns][0] + b0) * cscale;
            float v01 = (acc[ms][ns][1] + b1) * cscale;
            float v10 = (acc[ms][ns][2] + b0) * cscale;
            float v11 = (acc[ms][ns][3] + b1) * cscale;
            if (Cf) {
                *(float2*)(Cf + (size_t)row * D + col)       = make_float2(v00, v01);
                *(float2*)(Cf + (size_t)(row + 8) * D + col) = make_float2(v10, v11);
            } else {
                unsigned hh, ll;
                split_pack2(v00, v01, hh, ll);
                *(unsigned*)(Ch + (size_t)row * D + col) = hh;
                *(unsigned*)(Cl + (size_t)row * D + col) = ll;
                split_pack2(v10, v11, hh, ll);
                *(unsigned*)(Ch + (size_t)(row + 8) * D + col) = hh;
                *(unsigned*)(Cl + (size_t)(row + 8) * D + col) = ll;
            }
        }
    }
}

// ---------------------------------------------------------------------------
// Split-bf16 HMMA flash attention, TWO 16-row q-tiles per warp.
// CTA = 128 q-rows x (b,h), 128 threads = 4 warps; warp owns rows
// [wm*32, wm*32+32). K/V fragments shared across both tiles; softmax
// chains of the two tiles interleave. Q pre-scaled by 0.125*log2(e),
// softmax in base-2 (ex2.approx). P stays in registers.
// K/V double-buffered via cp.async (proven cadence).
// ---------------------------------------------------------------------------
constexpr int ASK  = 72;                 // plane stride (64 + 8)
constexpr int APL  = 64 * ASK;           // K/V plane elems
constexpr int QPL  = 128 * ASK;          // Q plane elems
// planes: Qh Ql (128-row) + 2 stages x (Kh Kl Vh Vl)
constexpr int ATTN_SMEM_BYTES = (2 * QPL + 8 * APL) * 2;   // 110592

__global__ __launch_bounds__(128, 2) void attn_tc_kernel(
    const bf16* __restrict__ Qh_g, const bf16* __restrict__ Ql_g,
    const bf16* __restrict__ Kh_g, const bf16* __restrict__ Kl_g,
    const bf16* __restrict__ Vh_g, const bf16* __restrict__ Vl_g,
    bf16* __restrict__ Oh_g, bf16* __restrict__ Ol_g)
{
    extern __shared__ __align__(16) char smraw[];
    bf16* Qh = (bf16*)smraw;
    bf16* Ql = Qh + QPL;
    bf16* KV = Ql + QPL;     // 2 stages x {Kh, Kl, Vh, Vl}

    const int t    = threadIdx.x;
    const int lane = t & 31;
    const int wm   = t >> 5;       // warp 0..3 — owns q rows [wm*32, wm*32+32)
    const int bh   = blockIdx.y;
    const int b    = bh / H;
    const int h    = bh % H;
    const int q0   = blockIdx.x * 128;

    const size_t rowBase = ((size_t)b * S + q0) * D + h * HD;
    const size_t kvBase  = ((size_t)b * S) * D + h * HD;

    auto load_kv = [&](int st, int kb) {
        bf16* base = KV + st * 4 * APL;
        #pragma unroll
        for (int i = 0; i < 4; i++) {
            int f   = t + i * 128;        // 0..511
            int rr  = f >> 3;             // 0..63
            int ce  = (f & 7) * 8;        // 0..56
            size_t g = kvBase + (size_t)(kb + rr) * D + ce;
            cpasync16(smem_u32(base + 0 * APL + rr * ASK + ce), Kh_g + g);
            cpasync16(smem_u32(base + 1 * APL + rr * ASK + ce), Kl_g + g);
            cpasync16(smem_u32(base + 2 * APL + rr * ASK + ce), Vh_g + g);
            cpasync16(smem_u32(base + 3 * APL + rr * ASK + ce), Vl_g + g);
        }
        cpcommit();
    };

    // Q loads (own group; 128 rows), then prefetch two K/V stages.
    #pragma unroll
    for (int i = 0; i < 8; i++) {
        int f   = t + i * 128;        // 0..1023
        int rr  = f >> 3;             // 0..127
        int ce  = (f & 7) * 8;
        size_t g = rowBase + (size_t)rr * D + ce;
        cpasync16(smem_u32(Qh + rr * ASK + ce), Qh_g + g);
        cpasync16(smem_u32(Ql + rr * ASK + ce), Ql_g + g);
    }
    cpcommit();
    load_kv(0, 0);
    load_kv(1, 64);

    // Per-tile softmax state (tiles tt=0,1; row pairs r, r+8 each)
    float mm[2][2], ll[2][2];
    #pragma unroll
    for (int i = 0; i < 2; i++) {
        mm[i][0] = -1e30f; mm[i][1] = -1e30f;
        ll[i][0] = 0.f;    ll[i][1] = 0.f;
    }
    float acc_o[2][8][4];
    #pragma unroll
    for (int tt = 0; tt < 2; tt++)
        #pragma unroll
        for (int i = 0; i < 8; i++)
            #pragma unroll
            for (int j = 0; j < 4; j++) acc_o[tt][i][j] = 0.f;

    for (int kb = 0; kb < S; kb += 64) {
        const int st = (kb >> 6) & 1;
        bf16* Kh = KV + st * 4 * APL;
        bf16* Kl = Kh + APL;
        bf16* Vh = Kl + APL;
        bf16* Vl = Vh + APL;

        cpwait<1>();     // current stage complete; next may be in flight
        __syncthreads();

        // ---- S = Q @ K^T : 2 tiles x (16 q x 64 keys), K-frags shared ----
        float acc_s[2][8][4];
        #pragma unroll
        for (int tt = 0; tt < 2; tt++)
            #pragma unroll
            for (int i = 0; i < 8; i++)
                #pragma unroll
                for (int j = 0; j < 4; j++) acc_s[tt][i][j] = 0.f;

        #pragma unroll
        for (int ks = 0; ks < 64; ks += 16) {
            unsigned ah[2][4], al[2][4], bhf[8][2], blf[8][2];
            ldmx4(ah[0], addrA<ASK>(Qh, wm * 32,      ks, lane));
            ldmx4(al[0], addrA<ASK>(Ql, wm * 32,      ks, lane));
            ldmx4(ah[1], addrA<ASK>(Qh, wm * 32 + 16, ks, lane));
            ldmx4(al[1], addrA<ASK>(Ql, wm * 32 + 16, ks, lane));
            #pragma unroll
            for (int nt = 0; nt < 4; nt++) {
                ldmx4(&bhf[nt * 2][0], addrB<ASK>(Kh, nt * 16, ks, lane));
                ldmx4(&blf[nt * 2][0], addrB<ASK>(Kl, nt * 16, ks, lane));
            }
            #pragma unroll
            for (int ns = 0; ns < 8; ns++) {
                mma16816(acc_s[0][ns], ah[0], bhf[ns]);
                mma16816(acc_s[1][ns], ah[1], bhf[ns]);
                mma16816(acc_s[0][ns], ah[0], blf[ns]);
                mma16816(acc_s[1][ns], ah[1], blf[ns]);
                mma16816(acc_s[0][ns], al[0], bhf[ns]);
                mma16816(acc_s[1][ns], al[1], bhf[ns]);
            }
        }

        // ---- warp-local online softmax, base-2 (Q pre-scaled) ----
        unsigned pa_h[2][4][4], pa_l[2][4][4];
        #pragma unroll
        for (int tt = 0; tt < 2; tt++) {
            float pm0 = -1e30f, pm8 = -1e30f;
            #pragma unroll
            for (int ns = 0; ns < 8; ns++) {
                pm0 = fmaxf(pm0, fmaxf(acc_s[tt][ns][0], acc_s[tt][ns][1]));
                pm8 = fmaxf(pm8, fmaxf(acc_s[tt][ns][2], acc_s[tt][ns][3]));
            }
            pm0 = fmaxf(pm0, __shfl_xor_sync(0xffffffffu, pm0, 1));
            pm0 = fmaxf(pm0, __shfl_xor_sync(0xffffffffu, pm0, 2));
            pm8 = fmaxf(pm8, __shfl_xor_sync(0xffffffffu, pm8, 1));
            pm8 = fmaxf(pm8, __shfl_xor_sync(0xffffffffu, pm8, 2));

            float mnew0 = fmaxf(mm[tt][0], pm0);
            float mnew8 = fmaxf(mm[tt][1], pm8);
            float alpha0 = ex2(mm[tt][0] - mnew0);
            float alpha8 = ex2(mm[tt][1] - mnew8);

            float ps0 = 0.f, ps8 = 0.f;
            #pragma unroll
            for (int ns = 0; ns < 8; ns++) {
                acc_s[tt][ns][0] = ex2(acc_s[tt][ns][0] - mnew0);
                acc_s[tt][ns][1] = ex2(acc_s[tt][ns][1] - mnew0);
                acc_s[tt][ns][2] = ex2(acc_s[tt][ns][2] - mnew8);
                acc_s[tt][ns][3] = ex2(acc_s[tt][ns][3] - mnew8);
                ps0 += acc_s[tt][ns][0] + acc_s[tt][ns][1];
                ps8 += acc_s[tt][ns][2] + acc_s[tt][ns][3];
            }
            ps0 += __shfl_xor_sync(0xffffffffu, ps0, 1);
            ps0 += __shfl_xor_sync(0xffffffffu, ps0, 2);
            ps8 += __shfl_xor_sync(0xffffffffu, ps8, 1);
            ps8 += __shfl_xor_sync(0xffffffffu, ps8, 2);

            ll[tt][0] = ll[tt][0] * alpha0 + ps0;
            ll[tt][1] = ll[tt][1] * alpha8 + ps8;
            mm[tt][0] = mnew0; mm[tt][1] = mnew8;

            // pack P into split-bf16 A-fragments in registers
            #pragma unroll
            for (int kk = 0; kk < 4; kk++) {
                split_pack2(acc_s[tt][2 * kk][0],     acc_s[tt][2 * kk][1],
                            pa_h[tt][kk][0], pa_l[tt][kk][0]);
                split_pack2(acc_s[tt][2 * kk][2],     acc_s[tt][2 * kk][3],
                            pa_h[tt][kk][1], pa_l[tt][kk][1]);
                split_pack2(acc_s[tt][2 * kk + 1][0], acc_s[tt][2 * kk + 1][1],
                            pa_h[tt][kk][2], pa_l[tt][kk][2]);
                split_pack2(acc_s[tt][2 * kk + 1][2], acc_s[tt][2 * kk + 1][3],
                            pa_h[tt][kk][3], pa_l[tt][kk][3]);
            }

            // rescale O accumulators
            #pragma unroll
            for (int ns = 0; ns < 8; ns++) {
                acc_o[tt][ns][0] *= alpha0; acc_o[tt][ns][1] *= alpha0;
                acc_o[tt][ns][2] *= alpha8; acc_o[tt][ns][3] *= alpha8;
            }
        }

        // ---- O += P @ V : 2 tiles x (16 q x 64 d), V-frags shared ----
        #pragma unroll
        for (int ks = 0; ks < 4; ks++) {
            unsigned bvh[8][2], bvl[8][2];
            #pragma unroll
            for (int nt = 0; nt < 4; nt++) {
                ldmx4t(&bvh[nt * 2][0], addrBT<ASK>(Vh, ks * 16, nt * 16, lane));
                ldmx4t(&bvl[nt * 2][0], addrBT<ASK>(Vl, ks * 16, nt * 16, lane));
            }
            #pragma unroll
            for (int ns = 0; ns < 8; ns++) {
                mma16816(acc_o[0][ns], pa_h[0][ks], bvh[ns]);
                mma16816(acc_o[1][ns], pa_h[1][ks], bvh[ns]);
                mma16816(acc_o[0][ns], pa_h[0][ks], bvl[ns]);
                mma16816(acc_o[1][ns], pa_h[1][ks], bvl[ns]);
                mma16816(acc_o[0][ns], pa_l[0][ks], bvh[ns]);
                mma16816(acc_o[1][ns], pa_l[1][ks], bvh[ns]);
            }
        }

        // All warps done reading stage st; refill with kb+128 (or empty
        // commit to keep the one-group-per-iteration cadence).
        __syncthreads();
        if (kb + 128 < S) load_kv(st, kb + 128);
        else              cpcommit();
    }

    // Epilogue: normalize, split-store to O planes [M][D]
    #pragma unroll
    for (int tt = 0; tt < 2; tt++) {
        float inv0 = 1.0f / ll[tt][0];
        float inv8 = 1.0f / ll[tt][1];
        size_t row = (size_t)b * S + q0 + wm * 32 + tt * 16 + (lane >> 2);
        #pragma unroll
        for (int ns = 0; ns < 8; ns++) {
            int col = h * HD + ns * 8 + (lane & 3) * 2;
            float v00 = acc_o[tt][ns][0] * inv0, v01 = acc_o[tt][ns][1] * inv0;
            float v10 = acc_o[tt][ns][2] * inv8, v11 = acc_o[tt][ns][3] * inv8;
            unsigned hh, llp;
            split_pack2(v00, v01, hh, llp);
            *(unsigned*)(Oh_g + row * D + col) = hh;
            *(unsigned*)(Ol_g + row * D + col) = llp;
            split_pack2(v10, v11, hh, llp);
            *(unsigned*)(Oh_g + (row + 8) * D + col) = hh;
            *(unsigned*)(Ol_g + (row + 8) * D + col) = llp;
        }
    }
}

// ---------------------------------------------------------------------------
// Launch
// ---------------------------------------------------------------------------
extern "C" void kernel_launch(void* const* d_in, const int* in_sizes, int n_in,
                              void* d_out, int out_size)
{
    const float* x  = (const float*)d_in[0];
    const float* Wq = (const float*)d_in[1];
    const float* bq = (const float*)d_in[2];
    const float* Wk = (const float*)d_in[3];
    const float* bk = (const float*)d_in[4];
    const float* Wv = (const float*)d_in[5];
    const float* bv = (const float*)d_in[6];
    const float* Wo = (const float*)d_in[7];
    const float* bo = (const float*)d_in[8];
    float* out = (float*)d_out;

    bf16 *xh, *xl, *Qh, *Ql, *Kh, *Kl, *Vh, *Vl, *Oh, *Ol, *WTh, *WTl;
    cudaGetSymbolAddress((void**)&xh, g_xh);
    cudaGetSymbolAddress((void**)&xl, g_xl);
    cudaGetSymbolAddress((void**)&Qh, g_Qh);
    cudaGetSymbolAddress((void**)&Ql, g_Ql);
    cudaGetSymbolAddress((void**)&Kh, g_Kh);
    cudaGetSymbolAddress((void**)&Kl, g_Kl);
    cudaGetSymbolAddress((void**)&Vh, g_Vh);
    cudaGetSymbolAddress((void**)&Vl, g_Vl);
    cudaGetSymbolAddress((void**)&Oh, g_Oh);
    cudaGetSymbolAddress((void**)&Ol, g_Ol);
    cudaGetSymbolAddress((void**)&WTh, g_WTh);
    cudaGetSymbolAddress((void**)&WTl, g_WTl);
    const size_t WSZ = (size_t)D * D;

    cudaFuncSetAttribute(gemm_tc, cudaFuncAttributeMaxDynamicSharedMemorySize,
                         GEMM_SMEM_BYTES);
    cudaFuncSetAttribute(attn_tc_kernel, cudaFuncAttributeMaxDynamicSharedMemorySize,
                         ATTN_SMEM_BYTES);

    // Prep: split x, transpose-split weights
    xprep_kernel<<<(M * D) / 1024, 256>>>(x, xh, xl);
    dim3 wgrid(D / 32, D / 32), wblk(32, 8);
    wprep_kernel<<<wgrid, wblk>>>(Wq, WTh + 0 * WSZ, WTl + 0 * WSZ);
    wprep_kernel<<<wgrid, wblk>>>(Wk, WTh + 1 * WSZ, WTl + 1 * WSZ);
    wprep_kernel<<<wgrid, wblk>>>(Wv, WTh + 2 * WSZ, WTl + 2 * WSZ);
    wprep_kernel<<<wgrid, wblk>>>(Wo, WTh + 3 * WSZ, WTl + 3 * WSZ);

    dim3 ggrid(D / 128, M / 128);   // (8, 32)

    // Projections -> split-bf16 Q/K/V planes.
    // Q is pre-scaled by 0.125*log2(e) so attention softmax runs in base 2.
    gemm_tc<<<ggrid, 256, GEMM_SMEM_BYTES>>>(xh, xl, WTh + 0 * WSZ, WTl + 0 * WSZ,
                                             bq, QSCALE, nullptr, Qh, Ql);
    gemm_tc<<<ggrid, 256, GEMM_SMEM_BYTES>>>(xh, xl, WTh + 1 * WSZ, WTl + 1 * WSZ,
                                             bk, 1.0f, nullptr, Kh, Kl);
    gemm_tc<<<ggrid, 256, GEMM_SMEM_BYTES>>>(xh, xl, WTh + 2 * WSZ, WTl + 2 * WSZ,
                                             bv, 1.0f, nullptr, Vh, Vl);

    // Attention -> split-bf16 O planes (128 q-rows per CTA)
    attn_tc_kernel<<<dim3(S / 128, B * H), 128, ATTN_SMEM_BYTES>>>(
        Qh, Ql, Kh, Kl, Vh, Vl, Oh, Ol);

    // Output projection -> fp32 out
    gemm_tc<<<ggrid, 256, GEMM_SMEM_BYTES>>>(Oh, Ol, WTh + 3 * WSZ, WTl + 3 * WSZ,
                                             bo, 1.0f, out, nullptr, nullptr);
}